// round 1
// baseline (speedup 1.0000x reference)
#include <cuda_runtime.h>
#include <cuda_bf16.h>

// Problem constants
#define BB 8
#define SS 2048
#define DD 768
#define HH 768

// Scratch (device globals — allocation-free rule)
__device__ float g_q[(long long)BB * SS * HH];
__device__ float g_k[(long long)BB * SS * HH];
__device__ float g_v[(long long)BB * SS * HH];   // holds q ⊙ v after V projection
__device__ float g_s[(long long)BB * SS * SS];   // scores / probs

#define BM 128
#define BN 128
#define BK 8
#define TM 8
#define TN 8
// 256 threads per block

// ---------------------------------------------------------------------------
// NN GEMM: C[z][m][n] = sum_k A[z][m][k] * B[z][k][n]  (+ bias[n]) (* mul[z][m][n])
// A row-major lda=K, B row-major ldb=N, C row-major ldc=N.
// ---------------------------------------------------------------------------
__global__ __launch_bounds__(256, 2)
void sgemm_nn(const float* __restrict__ A, const float* __restrict__ B,
              const float* __restrict__ bias, const float* __restrict__ mul,
              float* __restrict__ C,
              int M, int N, int K,
              long long sA, long long sB, long long sC)
{
    __shared__ float As[BK][BM];
    __shared__ float Bs[BK][BN];

    const int bx = blockIdx.x;           // N tile
    const int by = blockIdx.y;           // M tile
    const int z  = blockIdx.z;

    const float* Ab = A + (long long)z * sA + (long long)by * BM * K;
    const float* Bb = B + (long long)z * sB;
    float*       Cb = C + (long long)z * sC + (long long)by * BM * N + (long long)bx * BN;
    const float* Mb = mul ? (mul + (long long)z * sC + (long long)by * BM * N + (long long)bx * BN)
                          : nullptr;

    const int tid  = threadIdx.x;
    const int arow = tid >> 1;           // 0..127
    const int acol = (tid & 1) * 4;      // 0 or 4
    const int brow = tid >> 5;           // 0..7
    const int bcol = (tid & 31) * 4;     // 0..124

    const int tx = tid & 15;             // 0..15
    const int ty = tid >> 4;             // 0..15

    float acc[TM][TN];
    #pragma unroll
    for (int i = 0; i < TM; i++)
        #pragma unroll
        for (int j = 0; j < TN; j++)
            acc[i][j] = 0.0f;

    for (int k0 = 0; k0 < K; k0 += BK) {
        // A tile: 128 rows x 8 cols  -> As[col][row] (transposed)
        float4 a4 = *reinterpret_cast<const float4*>(Ab + (long long)arow * K + k0 + acol);
        As[acol + 0][arow] = a4.x;
        As[acol + 1][arow] = a4.y;
        As[acol + 2][arow] = a4.z;
        As[acol + 3][arow] = a4.w;
        // B tile: 8 rows x 128 cols -> Bs[row][col]
        float4 b4 = *reinterpret_cast<const float4*>(Bb + (long long)(k0 + brow) * N
                                                     + (long long)bx * BN + bcol);
        *reinterpret_cast<float4*>(&Bs[brow][bcol]) = b4;
        __syncthreads();

        #pragma unroll
        for (int kk = 0; kk < BK; kk++) {
            float4 a0 = *reinterpret_cast<const float4*>(&As[kk][ty * TM]);
            float4 a1 = *reinterpret_cast<const float4*>(&As[kk][ty * TM + 4]);
            float4 b0 = *reinterpret_cast<const float4*>(&Bs[kk][tx * TN]);
            float4 b1 = *reinterpret_cast<const float4*>(&Bs[kk][tx * TN + 4]);
            float ar[TM] = {a0.x, a0.y, a0.z, a0.w, a1.x, a1.y, a1.z, a1.w};
            float br[TN] = {b0.x, b0.y, b0.z, b0.w, b1.x, b1.y, b1.z, b1.w};
            #pragma unroll
            for (int i = 0; i < TM; i++)
                #pragma unroll
                for (int j = 0; j < TN; j++)
                    acc[i][j] = fmaf(ar[i], br[j], acc[i][j]);
        }
        __syncthreads();
    }

    // Epilogue
    #pragma unroll
    for (int i = 0; i < TM; i++) {
        int row = ty * TM + i;
        #pragma unroll
        for (int j = 0; j < TN; j++) {
            int col = tx * TN + j;
            float v = acc[i][j];
            if (bias) v += bias[(long long)bx * BN + col];
            if (Mb)   v *= Mb[(long long)row * N + col];
            Cb[(long long)row * N + col] = v;
        }
    }
}

// ---------------------------------------------------------------------------
// NT GEMM: C[z][i][j] = sum_h A[z][i][h] * B[z][j][h]
// A row-major [M,K], B row-major [N,K], C row-major [M,N].
// ---------------------------------------------------------------------------
__global__ __launch_bounds__(256, 2)
void sgemm_nt(const float* __restrict__ A, const float* __restrict__ B,
              float* __restrict__ C,
              int M, int N, int K,
              long long sA, long long sB, long long sC)
{
    __shared__ float As[BK][BM];
    __shared__ float Bs[BK][BN];

    const int bx = blockIdx.x;
    const int by = blockIdx.y;
    const int z  = blockIdx.z;

    const float* Ab = A + (long long)z * sA + (long long)by * BM * K;
    const float* Bb = B + (long long)z * sB + (long long)bx * BN * K;
    float*       Cb = C + (long long)z * sC + (long long)by * BM * N + (long long)bx * BN;

    const int tid  = threadIdx.x;
    const int arow = tid >> 1;
    const int acol = (tid & 1) * 4;

    const int tx = tid & 15;
    const int ty = tid >> 4;

    float acc[TM][TN];
    #pragma unroll
    for (int i = 0; i < TM; i++)
        #pragma unroll
        for (int j = 0; j < TN; j++)
            acc[i][j] = 0.0f;

    for (int k0 = 0; k0 < K; k0 += BK) {
        float4 a4 = *reinterpret_cast<const float4*>(Ab + (long long)arow * K + k0 + acol);
        As[acol + 0][arow] = a4.x;
        As[acol + 1][arow] = a4.y;
        As[acol + 2][arow] = a4.z;
        As[acol + 3][arow] = a4.w;
        // B tile: 128 j-rows x 8 h-cols, transposed into Bs[h][j]
        float4 b4 = *reinterpret_cast<const float4*>(Bb + (long long)arow * K + k0 + acol);
        Bs[acol + 0][arow] = b4.x;
        Bs[acol + 1][arow] = b4.y;
        Bs[acol + 2][arow] = b4.z;
        Bs[acol + 3][arow] = b4.w;
        __syncthreads();

        #pragma unroll
        for (int kk = 0; kk < BK; kk++) {
            float4 a0 = *reinterpret_cast<const float4*>(&As[kk][ty * TM]);
            float4 a1 = *reinterpret_cast<const float4*>(&As[kk][ty * TM + 4]);
            float4 b0 = *reinterpret_cast<const float4*>(&Bs[kk][tx * TN]);
            float4 b1 = *reinterpret_cast<const float4*>(&Bs[kk][tx * TN + 4]);
            float ar[TM] = {a0.x, a0.y, a0.z, a0.w, a1.x, a1.y, a1.z, a1.w};
            float br[TN] = {b0.x, b0.y, b0.z, b0.w, b1.x, b1.y, b1.z, b1.w};
            #pragma unroll
            for (int i = 0; i < TM; i++)
                #pragma unroll
                for (int j = 0; j < TN; j++)
                    acc[i][j] = fmaf(ar[i], br[j], acc[i][j]);
        }
        __syncthreads();
    }

    #pragma unroll
    for (int i = 0; i < TM; i++) {
        int row = ty * TM + i;
        #pragma unroll
        for (int j = 0; j < TN; j++) {
            Cb[(long long)row * N + tx * TN + j] = acc[i][j];
        }
    }
}

// ---------------------------------------------------------------------------
// Row softmax over rows of length L=2048 (in place). One block (256 thr) / row.
// ---------------------------------------------------------------------------
__global__ void softmax_rows(float* __restrict__ S, int L)
{
    const long long row = blockIdx.x;
    float* p = S + row * (long long)L;
    const int t = threadIdx.x;

    __shared__ float red[32];

    float v[8];
    float m = -1e30f;
    #pragma unroll
    for (int i = 0; i < 8; i++) {
        v[i] = p[t + i * 256];
        m = fmaxf(m, v[i]);
    }
    // block max
    #pragma unroll
    for (int o = 16; o > 0; o >>= 1) m = fmaxf(m, __shfl_xor_sync(0xffffffffu, m, o));
    if ((t & 31) == 0) red[t >> 5] = m;
    __syncthreads();
    if (t < 32) {
        float mm = (t < 8) ? red[t] : -1e30f;
        #pragma unroll
        for (int o = 16; o > 0; o >>= 1) mm = fmaxf(mm, __shfl_xor_sync(0xffffffffu, mm, o));
        if (t == 0) red[0] = mm;
    }
    __syncthreads();
    m = red[0];
    __syncthreads();

    float sum = 0.0f;
    #pragma unroll
    for (int i = 0; i < 8; i++) {
        v[i] = __expf(v[i] - m);
        sum += v[i];
    }
    #pragma unroll
    for (int o = 16; o > 0; o >>= 1) sum += __shfl_xor_sync(0xffffffffu, sum, o);
    if ((t & 31) == 0) red[t >> 5] = sum;
    __syncthreads();
    if (t < 32) {
        float ss = (t < 8) ? red[t] : 0.0f;
        #pragma unroll
        for (int o = 16; o > 0; o >>= 1) ss += __shfl_xor_sync(0xffffffffu, ss, o);
        if (t == 0) red[0] = ss;
    }
    __syncthreads();
    const float inv = 1.0f / red[0];

    #pragma unroll
    for (int i = 0; i < 8; i++) p[t + i * 256] = v[i] * inv;
}

// ---------------------------------------------------------------------------
extern "C" void kernel_launch(void* const* d_in, const int* in_sizes, int n_in,
                              void* d_out, int out_size)
{
    const float* x  = (const float*)d_in[0];
    const float* y  = (const float*)d_in[1];
    const float* Wq = (const float*)d_in[2];
    const float* bq = (const float*)d_in[3];
    const float* Wk = (const float*)d_in[4];
    const float* bk = (const float*)d_in[5];
    const float* Wv = (const float*)d_in[6];
    const float* bv = (const float*)d_in[7];
    float* out = (float*)d_out;

    float *pq, *pk, *pv, *ps;
    cudaGetSymbolAddress((void**)&pq, g_q);
    cudaGetSymbolAddress((void**)&pk, g_k);
    cudaGetSymbolAddress((void**)&pv, g_v);
    cudaGetSymbolAddress((void**)&ps, g_s);

    const int M = BB * SS;                       // 16384
    const long long sQ = (long long)SS * HH;     // per-batch Q/K/V stride
    const long long sS = (long long)SS * SS;     // per-batch score stride

    // QKV projections (V fused with elementwise multiply by Q -> V' = Q⊙V)
    dim3 gProj(HH / BN, M / BM, 1);
    sgemm_nn<<<gProj, 256>>>(x, Wq, bq, nullptr, pq, M, HH, DD, 0, 0, 0);
    sgemm_nn<<<gProj, 256>>>(x, Wk, bk, nullptr, pk, M, HH, DD, 0, 0, 0);
    sgemm_nn<<<gProj, 256>>>(y, Wv, bv, pq,      pv, M, HH, DD, 0, 0, 0);

    // scores = Q @ K^T  per batch
    dim3 gScore(SS / BN, SS / BM, BB);
    sgemm_nt<<<gScore, 256>>>(pq, pk, ps, SS, SS, HH, sQ, sQ, sS);

    // softmax over last dim
    softmax_rows<<<BB * SS, 256>>>(ps, SS);

    // context = P @ V'
    dim3 gCtx(HH / BN, SS / BM, BB);
    sgemm_nn<<<gCtx, 256>>>(ps, pv, nullptr, nullptr, out, SS, HH, SS, sS, sQ, sQ);
}

// round 3
// speedup vs baseline: 2.0753x; 2.0753x over previous
#include <cuda_runtime.h>
#include <cuda_bf16.h>
#include <cstdint>

// Problem constants
#define BB 8
#define SS 2048
#define DD 768
#define HH 768
#define MT (BB*SS)        // 16384
#define K3D (3*DD)        // 2304
#define K3S (3*SS)        // 6144

typedef long long ll;

// ---------------------------------------------------------------------------
// Scratch (device globals — allocation-free rule)
// ---------------------------------------------------------------------------
__device__ __align__(16) __nv_bfloat16 g_xcat[(ll)MT * K3D];   // x split  [M, 3D] (hi,lo,hi)
__device__ __align__(16) __nv_bfloat16 g_ycat[(ll)MT * K3D];   // y split
__device__ __align__(16) __nv_bfloat16 g_wt[3][(ll)HH * K3D];  // W^T split [H, 3D] (hi,hi,lo)
__device__ __align__(16) float g_q[(ll)MT * HH];
__device__ __align__(16) float g_k[(ll)MT * HH];
__device__ __align__(16) float g_v[(ll)MT * HH];               // V' = q ⊙ (yWv+bv)
__device__ __align__(16) __nv_bfloat16 g_qcat[(ll)MT * K3D];   // q split (hi,lo,hi)
__device__ __align__(16) __nv_bfloat16 g_kcat[(ll)MT * K3D];   // k split (hi,hi,lo)
__device__ __align__(16) __nv_bfloat16 g_vt[(ll)BB * HH * K3S];// V'^T split [b][H, 3S] (hi,hi,lo)
__device__ __align__(16) float g_s[(ll)BB * SS * SS];          // scores / probs
__device__ __align__(16) __nv_bfloat16 g_pcat[(ll)MT * K3S];   // probs split (hi,lo,hi)

// ---------------------------------------------------------------------------
// PTX helpers
// ---------------------------------------------------------------------------
__device__ __forceinline__ uint32_t s2u(const void* p) {
    return (uint32_t)__cvta_generic_to_shared(p);
}
__device__ __forceinline__ void ldmx4(uint32_t* r, uint32_t a) {
    asm volatile("ldmatrix.sync.aligned.m8n8.x4.shared.b16 {%0,%1,%2,%3}, [%4];"
                 : "=r"(r[0]), "=r"(r[1]), "=r"(r[2]), "=r"(r[3]) : "r"(a));
}
__device__ __forceinline__ void mmabf(float* c, const uint32_t* a, const uint32_t* b) {
    asm volatile("mma.sync.aligned.m16n8k16.row.col.f32.bf16.bf16.f32 "
                 "{%0,%1,%2,%3}, {%4,%5,%6,%7}, {%8,%9}, {%0,%1,%2,%3};"
                 : "+f"(c[0]), "+f"(c[1]), "+f"(c[2]), "+f"(c[3])
                 : "r"(a[0]), "r"(a[1]), "r"(a[2]), "r"(a[3]), "r"(b[0]), "r"(b[1]));
}

// ---------------------------------------------------------------------------
// bf16x3 NT GEMM: C[z][m][n] = sum_k A[z][m][k] * B[z][n][k]  (+bias[n]) (*mul)
// A: [rows, K] bf16 row-major (K-contig), B: [N, K] bf16 row-major (K-contig)
// 128x128x32 block tile, 8 warps (2x4), warp tile 64x32, mma m16n8k16.
// ---------------------------------------------------------------------------
#define KPAD 40  // smem row stride in bf16 (32 + 8 pad -> conflict-free ldmatrix)

__global__ __launch_bounds__(256, 2)
void gemm_bf16_nt(const __nv_bfloat16* __restrict__ A, ll sAz,
                  const __nv_bfloat16* __restrict__ B, ll sBz,
                  float* __restrict__ Cp, ll sCz,
                  const float* __restrict__ bias,
                  const float* __restrict__ mul,
                  int N, int K)
{
    __shared__ __nv_bfloat16 As[2][128 * KPAD];
    __shared__ __nv_bfloat16 Bs[2][128 * KPAD];

    const int tid = threadIdx.x;
    const int bx = blockIdx.x, by = blockIdx.y, z = blockIdx.z;
    const int lane = tid & 31, wid = tid >> 5;
    const int wm = (wid >> 2) * 64;   // warp m offset (0 / 64)
    const int wn = (wid & 3) * 32;    // warp n offset (0/32/64/96)

    const __nv_bfloat16* Ag = A + (ll)z * sAz + (ll)by * 128 * K;
    const __nv_bfloat16* Bg = B + (ll)z * sBz + (ll)bx * 128 * K;

    // global->smem loader mapping: 512 chunks of 16B; this thread: rows lr, lr+64
    const int lr = tid >> 2;
    const int lc = (tid & 3) * 8;

    float acc[4][4][4];
    #pragma unroll
    for (int i = 0; i < 4; i++)
        #pragma unroll
        for (int j = 0; j < 4; j++)
            #pragma unroll
            for (int q = 0; q < 4; q++)
                acc[i][j][q] = 0.0f;

    // fragment smem element offsets (per lane)
    const int aoff = (wm + (lane & 15)) * KPAD + ((lane >> 4) * 8);
    const int bg4 = lane >> 3;
    const int boff = (wn + ((bg4 >> 1) * 8) + (lane & 7)) * KPAD + (bg4 & 1) * 8;

    const int nk = K / 32;
    int4 ra0, ra1, rb0, rb1;

#define FETCH(kt) do {                                                                  \
    ra0 = *reinterpret_cast<const int4*>(Ag + (ll)lr * K + (kt) * 32 + lc);             \
    ra1 = *reinterpret_cast<const int4*>(Ag + (ll)(lr + 64) * K + (kt) * 32 + lc);      \
    rb0 = *reinterpret_cast<const int4*>(Bg + (ll)lr * K + (kt) * 32 + lc);             \
    rb1 = *reinterpret_cast<const int4*>(Bg + (ll)(lr + 64) * K + (kt) * 32 + lc);      \
} while (0)

#define STOREB(b) do {                                                                  \
    *reinterpret_cast<int4*>(&As[b][lr * KPAD + lc]) = ra0;                             \
    *reinterpret_cast<int4*>(&As[b][(lr + 64) * KPAD + lc]) = ra1;                      \
    *reinterpret_cast<int4*>(&Bs[b][lr * KPAD + lc]) = rb0;                             \
    *reinterpret_cast<int4*>(&Bs[b][(lr + 64) * KPAD + lc]) = rb1;                      \
} while (0)

#define COMPUTE(b) do {                                                                 \
    uint32_t abase = s2u(&As[b][0]);                                                    \
    uint32_t bbase = s2u(&Bs[b][0]);                                                    \
    _Pragma("unroll")                                                                   \
    for (int ks = 0; ks < 2; ks++) {                                                    \
        uint32_t af[4][4], bfr[2][4];                                                   \
        _Pragma("unroll")                                                               \
        for (int mi = 0; mi < 4; mi++)                                                  \
            ldmx4(af[mi], abase + 2 * (aoff + mi * 16 * KPAD + ks * 16));               \
        _Pragma("unroll")                                                               \
        for (int bj = 0; bj < 2; bj++)                                                  \
            ldmx4(bfr[bj], bbase + 2 * (boff + bj * 16 * KPAD + ks * 16));              \
        _Pragma("unroll")                                                               \
        for (int mi = 0; mi < 4; mi++)                                                  \
            _Pragma("unroll")                                                           \
            for (int ni = 0; ni < 4; ni++)                                              \
                mmabf(acc[mi][ni], af[mi], &bfr[ni >> 1][(ni & 1) * 2]);                \
    }                                                                                   \
} while (0)

    FETCH(0);
    STOREB(0);
    __syncthreads();

    for (int kt = 0; kt < nk; kt++) {
        const int b = kt & 1;
        if (kt + 1 < nk) FETCH(kt + 1);
        COMPUTE(b);
        if (kt + 1 < nk) {
            STOREB(b ^ 1);
            __syncthreads();
        }
    }

    // epilogue
    const int gq = lane >> 2, tig = lane & 3;
    float* Cz = Cp + (ll)z * sCz;
    const float* Mz = mul ? (mul + (ll)z * sCz) : nullptr;
    #pragma unroll
    for (int mi = 0; mi < 4; mi++) {
        #pragma unroll
        for (int ni = 0; ni < 4; ni++) {
            int row = by * 128 + wm + mi * 16 + gq;
            int col = bx * 128 + wn + ni * 8 + tig * 2;
            float v0 = acc[mi][ni][0], v1 = acc[mi][ni][1];
            float v2 = acc[mi][ni][2], v3 = acc[mi][ni][3];
            if (bias) {
                float b0 = bias[col], b1 = bias[col + 1];
                v0 += b0; v1 += b1; v2 += b0; v3 += b1;
            }
            ll o0 = (ll)row * N + col;
            ll o1 = o0 + 8LL * N;
            if (Mz) {
                v0 *= Mz[o0]; v1 *= Mz[o0 + 1];
                v2 *= Mz[o1]; v3 *= Mz[o1 + 1];
            }
            float2 r01; r01.x = v0; r01.y = v1;
            float2 r23; r23.x = v2; r23.y = v3;
            *reinterpret_cast<float2*>(Cz + o0) = r01;
            *reinterpret_cast<float2*>(Cz + o1) = r23;
        }
    }
#undef FETCH
#undef STOREB
#undef COMPUTE
}

// ---------------------------------------------------------------------------
// fp32 -> bf16x3 split, concatenated along columns.
// loSlot==1: slots (hi, lo, hi)  [A-side]    loSlot==2: slots (hi, hi, lo) [B-side]
// src [R, C] -> dst [R, 3C]. grid (C/256, R)
// ---------------------------------------------------------------------------
__global__ void cat_split(const float* __restrict__ src, __nv_bfloat16* __restrict__ dst,
                          int C, int loSlot)
{
    const ll r = blockIdx.y;
    const int c = blockIdx.x * 256 + threadIdx.x;
    float x = src[r * C + c];
    __nv_bfloat16 hi = __float2bfloat16(x);
    __nv_bfloat16 lo = __float2bfloat16(x - __bfloat162float(hi));
    __nv_bfloat16* d = dst + r * (3LL * C);
    d[c] = hi;
    d[C + c]     = (loSlot == 1) ? lo : hi;
    d[2LL * C + c] = (loSlot == 1) ? hi : lo;
}

// ---------------------------------------------------------------------------
// Transposed bf16x3 split (B-side order hi,hi,lo):
// src [R, C] fp32 per z -> dst [C, 3R] bf16 per z. grid (C/32, R/32, Z), block (32,8)
// ---------------------------------------------------------------------------
__global__ void cat_split_t(const float* __restrict__ src, __nv_bfloat16* __restrict__ dst,
                            int R, int C, ll sz, ll dz)
{
    __shared__ float t[32][33];
    const int z = blockIdx.z;
    const float* s = src + (ll)z * sz;
    __nv_bfloat16* d = dst + (ll)z * dz;
    const int c0 = blockIdx.x * 32, r0 = blockIdx.y * 32;
    const int tx = threadIdx.x, ty = threadIdx.y;

    #pragma unroll
    for (int i = 0; i < 4; i++)
        t[ty + 8 * i][tx] = s[(ll)(r0 + ty + 8 * i) * C + c0 + tx];
    __syncthreads();
    #pragma unroll
    for (int i = 0; i < 4; i++) {
        float x = t[tx][ty + 8 * i];
        __nv_bfloat16 hi = __float2bfloat16(x);
        __nv_bfloat16 lo = __float2bfloat16(x - __bfloat162float(hi));
        __nv_bfloat16* dr = d + (ll)(c0 + ty + 8 * i) * (3LL * R);
        dr[r0 + tx]          = hi;
        dr[R + r0 + tx]      = hi;
        dr[2LL * R + r0 + tx] = lo;
    }
}

// ---------------------------------------------------------------------------
// Row softmax over rows of length 2048 (in place). One 256-thread block / row.
// ---------------------------------------------------------------------------
__global__ void softmax_rows(float* __restrict__ S, int L)
{
    const ll row = blockIdx.x;
    float* p = S + row * (ll)L;
    const int t = threadIdx.x;
    __shared__ float red[32];

    float v[8];
    float m = -1e30f;
    #pragma unroll
    for (int i = 0; i < 8; i++) {
        v[i] = p[t + i * 256];
        m = fmaxf(m, v[i]);
    }
    #pragma unroll
    for (int o = 16; o > 0; o >>= 1) m = fmaxf(m, __shfl_xor_sync(0xffffffffu, m, o));
    if ((t & 31) == 0) red[t >> 5] = m;
    __syncthreads();
    if (t < 32) {
        float mm = (t < 8) ? red[t] : -1e30f;
        #pragma unroll
        for (int o = 16; o > 0; o >>= 1) mm = fmaxf(mm, __shfl_xor_sync(0xffffffffu, mm, o));
        if (t == 0) red[0] = mm;
    }
    __syncthreads();
    m = red[0];
    __syncthreads();

    float sum = 0.0f;
    #pragma unroll
    for (int i = 0; i < 8; i++) {
        v[i] = __expf(v[i] - m);
        sum += v[i];
    }
    #pragma unroll
    for (int o = 16; o > 0; o >>= 1) sum += __shfl_xor_sync(0xffffffffu, sum, o);
    if ((t & 31) == 0) red[t >> 5] = sum;
    __syncthreads();
    if (t < 32) {
        float ss = (t < 8) ? red[t] : 0.0f;
        #pragma unroll
        for (int o = 16; o > 0; o >>= 1) ss += __shfl_xor_sync(0xffffffffu, ss, o);
        if (t == 0) red[0] = ss;
    }
    __syncthreads();
    const float inv = 1.0f / red[0];
    #pragma unroll
    for (int i = 0; i < 8; i++) p[t + i * 256] = v[i] * inv;
}

// ---------------------------------------------------------------------------
extern "C" void kernel_launch(void* const* d_in, const int* in_sizes, int n_in,
                              void* d_out, int out_size)
{
    const float* x  = (const float*)d_in[0];
    const float* y  = (const float*)d_in[1];
    const float* Wq = (const float*)d_in[2];
    const float* bq = (const float*)d_in[3];
    const float* Wk = (const float*)d_in[4];
    const float* bk = (const float*)d_in[5];
    const float* Wv = (const float*)d_in[6];
    const float* bv = (const float*)d_in[7];
    float* out = (float*)d_out;

    __nv_bfloat16 *pxcat, *pycat, *pwt, *pqcat, *pkcat, *pvt, *ppcat;
    float *pq, *pk, *pv, *ps;
    cudaGetSymbolAddress((void**)&pxcat, g_xcat);
    cudaGetSymbolAddress((void**)&pycat, g_ycat);
    cudaGetSymbolAddress((void**)&pwt,   g_wt);
    cudaGetSymbolAddress((void**)&pq,    g_q);
    cudaGetSymbolAddress((void**)&pk,    g_k);
    cudaGetSymbolAddress((void**)&pv,    g_v);
    cudaGetSymbolAddress((void**)&pqcat, g_qcat);
    cudaGetSymbolAddress((void**)&pkcat, g_kcat);
    cudaGetSymbolAddress((void**)&pvt,   g_vt);
    cudaGetSymbolAddress((void**)&ps,    g_s);
    cudaGetSymbolAddress((void**)&ppcat, g_pcat);

    const ll wtStride = (ll)HH * K3D;

    // 1. split inputs
    cat_split<<<dim3(DD / 256, MT), 256>>>(x, pxcat, DD, 1);
    cat_split<<<dim3(DD / 256, MT), 256>>>(y, pycat, DD, 1);
    cat_split_t<<<dim3(HH / 32, DD / 32, 1), dim3(32, 8)>>>(Wq, pwt + 0 * wtStride, DD, HH, 0, 0);
    cat_split_t<<<dim3(HH / 32, DD / 32, 1), dim3(32, 8)>>>(Wk, pwt + 1 * wtStride, DD, HH, 0, 0);
    cat_split_t<<<dim3(HH / 32, DD / 32, 1), dim3(32, 8)>>>(Wv, pwt + 2 * wtStride, DD, HH, 0, 0);

    // 2. projections (bf16x3): q, k, v' (v fused with ⊙q)
    dim3 gProj(HH / 128, MT / 128, 1);
    gemm_bf16_nt<<<gProj, 256>>>(pxcat, 0, pwt + 0 * wtStride, 0, pq, 0, bq, nullptr, HH, K3D);
    gemm_bf16_nt<<<gProj, 256>>>(pxcat, 0, pwt + 1 * wtStride, 0, pk, 0, bk, nullptr, HH, K3D);
    gemm_bf16_nt<<<gProj, 256>>>(pycat, 0, pwt + 2 * wtStride, 0, pv, 0, bv, pq,      HH, K3D);

    // 3. split q (A-side) and k (B-side)
    cat_split<<<dim3(HH / 256, MT), 256>>>(pq, pqcat, HH, 1);
    cat_split<<<dim3(HH / 256, MT), 256>>>(pk, pkcat, HH, 2);

    // 4. scores = Q K^T (batched)
    dim3 gScore(SS / 128, SS / 128, BB);
    gemm_bf16_nt<<<gScore, 256>>>(pqcat, (ll)SS * K3D, pkcat, (ll)SS * K3D,
                                  ps, (ll)SS * SS, nullptr, nullptr, SS, K3D);

    // 5. softmax
    softmax_rows<<<BB * SS, 256>>>(ps, SS);

    // 6. split probs (A-side) and V'^T (B-side, transposed)
    cat_split<<<dim3(SS / 256, MT), 256>>>(ps, ppcat, SS, 1);
    cat_split_t<<<dim3(HH / 32, SS / 32, BB), dim3(32, 8)>>>(pv, pvt, SS, HH,
                                                             (ll)SS * HH, (ll)HH * K3S);

    // 7. context = P V'
    dim3 gCtx(HH / 128, SS / 128, BB);
    gemm_bf16_nt<<<gCtx, 256>>>(ppcat, (ll)SS * K3S, pvt, (ll)HH * K3S,
                                out, (ll)SS * HH, nullptr, nullptr, HH, K3S);
}

// round 8
// speedup vs baseline: 2.4158x; 1.1640x over previous
#include <cuda_runtime.h>
#include <cuda_bf16.h>
#include <cstdint>

// Problem constants
#define BB 8
#define SS 2048
#define DD 768
#define HH 768
#define MT (BB*SS)        // 16384
#define K3D (3*DD)        // 2304
#define K3S (3*SS)        // 6144

typedef long long ll;

// ---------------------------------------------------------------------------
// Scratch (device globals — allocation-free rule)
// ---------------------------------------------------------------------------
__device__ __align__(16) __nv_bfloat16 g_xcat[(ll)MT * K3D];
__device__ __align__(16) __nv_bfloat16 g_ycat[(ll)MT * K3D];
__device__ __align__(16) __nv_bfloat16 g_wt[3][(ll)HH * K3D];
__device__ __align__(16) float g_q[(ll)MT * HH];
__device__ __align__(16) float g_v[(ll)MT * HH];              // V' = q ⊙ (yWv+bv)
__device__ __align__(16) __nv_bfloat16 g_qcat[(ll)MT * K3D];  // (hi,lo,hi)
__device__ __align__(16) __nv_bfloat16 g_kcat[(ll)MT * K3D];  // (hi,hi,lo)
__device__ __align__(16) __nv_bfloat16 g_vt[(ll)BB * HH * K3S];
__device__ __align__(16) float g_s[(ll)BB * SS * SS];
__device__ __align__(16) __nv_bfloat16 g_pcat[(ll)MT * K3S];  // (hi,lo,hi)

// ---------------------------------------------------------------------------
// PTX helpers
// ---------------------------------------------------------------------------
__device__ __forceinline__ uint32_t s2u(const void* p) {
    return (uint32_t)__cvta_generic_to_shared(p);
}
__device__ __forceinline__ void ldmx4(uint32_t* r, uint32_t a) {
    asm volatile("ldmatrix.sync.aligned.m8n8.x4.shared.b16 {%0,%1,%2,%3}, [%4];"
                 : "=r"(r[0]), "=r"(r[1]), "=r"(r[2]), "=r"(r[3]) : "r"(a));
}
__device__ __forceinline__ void mmabf(float* c, const uint32_t* a, const uint32_t* b) {
    asm volatile("mma.sync.aligned.m16n8k16.row.col.f32.bf16.bf16.f32 "
                 "{%0,%1,%2,%3}, {%4,%5,%6,%7}, {%8,%9}, {%0,%1,%2,%3};"
                 : "+f"(c[0]), "+f"(c[1]), "+f"(c[2]), "+f"(c[3])
                 : "r"(a[0]), "r"(a[1]), "r"(a[2]), "r"(a[3]), "r"(b[0]), "r"(b[1]));
}
__device__ __forceinline__ void cp16(uint32_t dst, const void* src) {
    asm volatile("cp.async.cg.shared.global [%0], [%1], 16;"
                 :: "r"(dst), "l"(src) : "memory");
}
__device__ __forceinline__ void cp_commit() {
    asm volatile("cp.async.commit_group;" ::: "memory");
}

// ---------------------------------------------------------------------------
// bf16x3 NT GEMM (mma.sync), cp.async 4-stage ring:
//   C[z][m][n] = sum_k A[z][m][k]*B[z][n][k] (+bias[n]) (*mul)
// A: [*,K] K-contig, B: [N,K] K-contig. Block tile 128x128x32, 8 warps (2x4),
// warp tile 64x32. Epilogue: optional fp32 C and/or bf16x3 concat
// (catLo: 1=(hi,lo,hi) A-side, 2=(hi,hi,lo) B-side).
// ---------------------------------------------------------------------------
#define KPAD 40                        // smem row stride (elems): 32 + 8 pad
#define MAT_BYTES (128 * KPAD * 2)     // 10240
#define STG_BYTES (2 * MAT_BYTES)      // 20480 (A + B)
#define NSTAGE 4
#define GEMM_SMEM (NSTAGE * STG_BYTES) // 81920

__device__ __forceinline__ void issue_stage(const __nv_bfloat16* Ag,
                                            const __nv_bfloat16* Bg,
                                            int K, int kt, uint32_t sA,
                                            int lr, int lc)
{
    const ll k0 = (ll)kt * 32;
    const uint32_t sB = sA + MAT_BYTES;
    cp16(sA + lr * (KPAD * 2) + lc * 2,          Ag + (ll)lr * K + k0 + lc);
    cp16(sA + (lr + 64) * (KPAD * 2) + lc * 2,   Ag + (ll)(lr + 64) * K + k0 + lc);
    cp16(sB + lr * (KPAD * 2) + lc * 2,          Bg + (ll)lr * K + k0 + lc);
    cp16(sB + (lr + 64) * (KPAD * 2) + lc * 2,   Bg + (ll)(lr + 64) * K + k0 + lc);
    cp_commit();
}

__global__ __launch_bounds__(256, 2)
void gemm_bf16_nt(const __nv_bfloat16* __restrict__ A, ll sAz,
                  const __nv_bfloat16* __restrict__ B, ll sBz,
                  float* __restrict__ Cf, __nv_bfloat16* __restrict__ Ccat, ll sCz,
                  const float* __restrict__ bias,
                  const float* __restrict__ mul,
                  int N, int K, int catLo)
{
    extern __shared__ char dyn[];
    const uint32_t sbase = s2u(dyn);

    const int tid = threadIdx.x;
    const int bx = blockIdx.x, by = blockIdx.y, z = blockIdx.z;
    const int lane = tid & 31, wid = tid >> 5;
    const int wm = (wid >> 2) * 64;
    const int wn = (wid & 3) * 32;

    const __nv_bfloat16* Ag = A + (ll)z * sAz + (ll)by * 128 * K;
    const __nv_bfloat16* Bg = B + (ll)z * sBz + (ll)bx * 128 * K;

    const int lr = tid >> 2;
    const int lc = (tid & 3) * 8;

    float acc[4][4][4];
    #pragma unroll
    for (int i = 0; i < 4; i++)
        #pragma unroll
        for (int j = 0; j < 4; j++)
            #pragma unroll
            for (int q = 0; q < 4; q++)
                acc[i][j][q] = 0.0f;

    // fragment smem element offsets (per lane) — proven conflict-free w/ KPAD=40
    const int aoff = (wm + (lane & 15)) * KPAD + ((lane >> 4) * 8);
    const int bg4 = lane >> 3;
    const int boff = (wn + ((bg4 >> 1) * 8) + (lane & 7)) * KPAD + (bg4 & 1) * 8;

    const int nk = K / 32;

    // prologue: 3 stages in flight
    issue_stage(Ag, Bg, K, 0, sbase + 0 * STG_BYTES, lr, lc);
    issue_stage(Ag, Bg, K, 1, sbase + 1 * STG_BYTES, lr, lc);
    issue_stage(Ag, Bg, K, 2, sbase + 2 * STG_BYTES, lr, lc);

    for (int kt = 0; kt < nk; kt++) {
        asm volatile("cp.async.wait_group %0;" :: "n"(2) : "memory");
        __syncthreads();
        if (kt + 3 < nk)
            issue_stage(Ag, Bg, K, kt + 3, sbase + ((kt + 3) & 3) * STG_BYTES, lr, lc);

        const uint32_t abase = sbase + (kt & 3) * STG_BYTES;
        const uint32_t bbase = abase + MAT_BYTES;
        #pragma unroll
        for (int ks = 0; ks < 2; ks++) {
            uint32_t af[4][4], bfr[2][4];
            #pragma unroll
            for (int mi = 0; mi < 4; mi++)
                ldmx4(af[mi], abase + 2 * (aoff + mi * 16 * KPAD + ks * 16));
            #pragma unroll
            for (int bj = 0; bj < 2; bj++)
                ldmx4(bfr[bj], bbase + 2 * (boff + bj * 16 * KPAD + ks * 16));
            #pragma unroll
            for (int mi = 0; mi < 4; mi++)
                #pragma unroll
                for (int ni = 0; ni < 4; ni++)
                    mmabf(acc[mi][ni], af[mi], &bfr[ni >> 1][(ni & 1) * 2]);
        }
    }

    // --- epilogue ---
    const int gq = lane >> 2, tig = lane & 3;
    float* Cz = Cf ? (Cf + (ll)z * sCz) : nullptr;
    const float* Mz = mul ? (mul + (ll)z * sCz) : nullptr;

    #pragma unroll
    for (int mi = 0; mi < 4; mi++) {
        #pragma unroll
        for (int ni = 0; ni < 4; ni++) {
            const int row = by * 128 + wm + mi * 16 + gq;
            const int col = bx * 128 + wn + ni * 8 + tig * 2;
            float v0 = acc[mi][ni][0], v1 = acc[mi][ni][1];
            float v2 = acc[mi][ni][2], v3 = acc[mi][ni][3];
            if (bias) {
                float b0 = bias[col], b1 = bias[col + 1];
                v0 += b0; v1 += b1; v2 += b0; v3 += b1;
            }
            const ll o0 = (ll)row * N + col;
            const ll o1 = o0 + 8LL * N;
            if (Mz) {
                v0 *= Mz[o0]; v1 *= Mz[o0 + 1];
                v2 *= Mz[o1]; v3 *= Mz[o1 + 1];
            }
            if (Cz) {
                float2 r01; r01.x = v0; r01.y = v1;
                float2 r23; r23.x = v2; r23.y = v3;
                *reinterpret_cast<float2*>(Cz + o0) = r01;
                *reinterpret_cast<float2*>(Cz + o1) = r23;
            }
            if (Ccat) {
                __nv_bfloat16* K0 = Ccat + (ll)row * (3LL * N) + col;
                __nv_bfloat16* K1 = Ccat + (ll)(row + 8) * (3LL * N) + col;
                __nv_bfloat16 h0 = __float2bfloat16(v0);
                __nv_bfloat16 h1 = __float2bfloat16(v1);
                __nv_bfloat16 h2 = __float2bfloat16(v2);
                __nv_bfloat16 h3 = __float2bfloat16(v3);
                __nv_bfloat16 l0 = __float2bfloat16(v0 - __bfloat162float(h0));
                __nv_bfloat16 l1 = __float2bfloat16(v1 - __bfloat162float(h1));
                __nv_bfloat16 l2 = __float2bfloat16(v2 - __bfloat162float(h2));
                __nv_bfloat16 l3 = __float2bfloat16(v3 - __bfloat162float(h3));
                __nv_bfloat162 hp0; hp0.x = h0; hp0.y = h1;
                __nv_bfloat162 hp1; hp1.x = h2; hp1.y = h3;
                __nv_bfloat162 lp0; lp0.x = l0; lp0.y = l1;
                __nv_bfloat162 lp1; lp1.x = l2; lp1.y = l3;
                *reinterpret_cast<__nv_bfloat162*>(K0) = hp0;
                *reinterpret_cast<__nv_bfloat162*>(K1) = hp1;
                *reinterpret_cast<__nv_bfloat162*>(K0 + N) = (catLo == 1) ? lp0 : hp0;
                *reinterpret_cast<__nv_bfloat162*>(K1 + N) = (catLo == 1) ? lp1 : hp1;
                *reinterpret_cast<__nv_bfloat162*>(K0 + 2 * N) = (catLo == 1) ? hp0 : lp0;
                *reinterpret_cast<__nv_bfloat162*>(K1 + 2 * N) = (catLo == 1) ? hp1 : lp1;
            }
        }
    }
}

// ---------------------------------------------------------------------------
// fp32 -> bf16x3 split (A-side: hi,lo,hi), src [R,C] -> dst [R,3C]
// ---------------------------------------------------------------------------
__global__ void cat_split(const float* __restrict__ src, __nv_bfloat16* __restrict__ dst,
                          int C)
{
    const ll r = blockIdx.y;
    const int c = blockIdx.x * 256 + threadIdx.x;
    float x = src[r * C + c];
    __nv_bfloat16 hi = __float2bfloat16(x);
    __nv_bfloat16 lo = __float2bfloat16(x - __bfloat162float(hi));
    __nv_bfloat16* d = dst + r * (3LL * C);
    d[c] = hi;
    d[C + c] = lo;
    d[2LL * C + c] = hi;
}

// ---------------------------------------------------------------------------
// Transposed bf16x3 split (B-side: hi,hi,lo): src [R,C] fp32 -> dst [C,3R]
// ---------------------------------------------------------------------------
__global__ void cat_split_t(const float* __restrict__ src, __nv_bfloat16* __restrict__ dst,
                            int R, int C, ll sz, ll dz)
{
    __shared__ float t[32][33];
    const int z = blockIdx.z;
    const float* s = src + (ll)z * sz;
    __nv_bfloat16* d = dst + (ll)z * dz;
    const int c0 = blockIdx.x * 32, r0 = blockIdx.y * 32;
    const int tx = threadIdx.x, ty = threadIdx.y;

    #pragma unroll
    for (int i = 0; i < 4; i++)
        t[ty + 8 * i][tx] = s[(ll)(r0 + ty + 8 * i) * C + c0 + tx];
    __syncthreads();
    #pragma unroll
    for (int i = 0; i < 4; i++) {
        float x = t[tx][ty + 8 * i];
        __nv_bfloat16 hi = __float2bfloat16(x);
        __nv_bfloat16 lo = __float2bfloat16(x - __bfloat162float(hi));
        __nv_bfloat16* dr = d + (ll)(c0 + ty + 8 * i) * (3LL * R);
        dr[r0 + tx] = hi;
        dr[R + r0 + tx] = hi;
        dr[2LL * R + r0 + tx] = lo;
    }
}

// ---------------------------------------------------------------------------
// Fused softmax + bf16x3 split (A-side): scores row fp32 -> pcat row [3*SS]
// ---------------------------------------------------------------------------
__global__ void softmax_split(const float* __restrict__ S, __nv_bfloat16* __restrict__ P)
{
    const ll row = blockIdx.x;
    const float* p = S + row * (ll)SS;
    __nv_bfloat16* d = P + row * (ll)K3S;
    const int t = threadIdx.x;
    __shared__ float red[32];

    float v[8];
    float m = -1e30f;
    #pragma unroll
    for (int i = 0; i < 8; i++) {
        v[i] = p[t + i * 256];
        m = fmaxf(m, v[i]);
    }
    #pragma unroll
    for (int o = 16; o > 0; o >>= 1) m = fmaxf(m, __shfl_xor_sync(0xffffffffu, m, o));
    if ((t & 31) == 0) red[t >> 5] = m;
    __syncthreads();
    if (t < 32) {
        float mm = (t < 8) ? red[t] : -1e30f;
        #pragma unroll
        for (int o = 16; o > 0; o >>= 1) mm = fmaxf(mm, __shfl_xor_sync(0xffffffffu, mm, o));
        if (t == 0) red[0] = mm;
    }
    __syncthreads();
    m = red[0];
    __syncthreads();

    float sum = 0.0f;
    #pragma unroll
    for (int i = 0; i < 8; i++) {
        v[i] = __expf(v[i] - m);
        sum += v[i];
    }
    #pragma unroll
    for (int o = 16; o > 0; o >>= 1) sum += __shfl_xor_sync(0xffffffffu, sum, o);
    if ((t & 31) == 0) red[t >> 5] = sum;
    __syncthreads();
    if (t < 32) {
        float ss = (t < 8) ? red[t] : 0.0f;
        #pragma unroll
        for (int o = 16; o > 0; o >>= 1) ss += __shfl_xor_sync(0xffffffffu, ss, o);
        if (t == 0) red[0] = ss;
    }
    __syncthreads();
    const float inv = 1.0f / red[0];

    #pragma unroll
    for (int i = 0; i < 8; i++) {
        const int c = t + i * 256;
        float pr = v[i] * inv;
        __nv_bfloat16 hi = __float2bfloat16(pr);
        __nv_bfloat16 lo = __float2bfloat16(pr - __bfloat162float(hi));
        d[c] = hi;
        d[SS + c] = lo;
        d[2 * SS + c] = hi;
    }
}

// ---------------------------------------------------------------------------
extern "C" void kernel_launch(void* const* d_in, const int* in_sizes, int n_in,
                              void* d_out, int out_size)
{
    const float* x  = (const float*)d_in[0];
    const float* y  = (const float*)d_in[1];
    const float* Wq = (const float*)d_in[2];
    const float* bq = (const float*)d_in[3];
    const float* Wk = (const float*)d_in[4];
    const float* bk = (const float*)d_in[5];
    const float* Wv = (const float*)d_in[6];
    const float* bv = (const float*)d_in[7];
    float* out = (float*)d_out;

    __nv_bfloat16 *pxcat, *pycat, *pwt, *pqcat, *pkcat, *pvt, *ppcat;
    float *pq, *pv, *ps;
    cudaGetSymbolAddress((void**)&pxcat, g_xcat);
    cudaGetSymbolAddress((void**)&pycat, g_ycat);
    cudaGetSymbolAddress((void**)&pwt,   g_wt);
    cudaGetSymbolAddress((void**)&pq,    g_q);
    cudaGetSymbolAddress((void**)&pv,    g_v);
    cudaGetSymbolAddress((void**)&pqcat, g_qcat);
    cudaGetSymbolAddress((void**)&pkcat, g_kcat);
    cudaGetSymbolAddress((void**)&pvt,   g_vt);
    cudaGetSymbolAddress((void**)&ps,    g_s);
    cudaGetSymbolAddress((void**)&ppcat, g_pcat);

    cudaFuncSetAttribute(gemm_bf16_nt, cudaFuncAttributeMaxDynamicSharedMemorySize,
                         GEMM_SMEM);

    const ll wtStride = (ll)HH * K3D;

    // 1. split inputs + weights
    cat_split<<<dim3(DD / 256, MT), 256>>>(x, pxcat, DD);
    cat_split<<<dim3(DD / 256, MT), 256>>>(y, pycat, DD);
    cat_split_t<<<dim3(HH / 32, DD / 32, 1), dim3(32, 8)>>>(Wq, pwt + 0 * wtStride, DD, HH, 0, 0);
    cat_split_t<<<dim3(HH / 32, DD / 32, 1), dim3(32, 8)>>>(Wk, pwt + 1 * wtStride, DD, HH, 0, 0);
    cat_split_t<<<dim3(HH / 32, DD / 32, 1), dim3(32, 8)>>>(Wv, pwt + 2 * wtStride, DD, HH, 0, 0);

    // 2. projections (fused split epilogues)
    dim3 gProj(HH / 128, MT / 128, 1);
    // Q: fp32 q (for gating) + qcat (hi,lo,hi)
    gemm_bf16_nt<<<gProj, 256, GEMM_SMEM>>>(pxcat, 0, pwt + 0 * wtStride, 0,
                                            pq, pqcat, 0, bq, nullptr, HH, K3D, 1);
    // K: kcat only (hi,hi,lo)
    gemm_bf16_nt<<<gProj, 256, GEMM_SMEM>>>(pxcat, 0, pwt + 1 * wtStride, 0,
                                            nullptr, pkcat, 0, bk, nullptr, HH, K3D, 2);
    // V: fp32 v' = (yWv+bv) ⊙ q
    gemm_bf16_nt<<<gProj, 256, GEMM_SMEM>>>(pycat, 0, pwt + 2 * wtStride, 0,
                                            pv, nullptr, 0, bv, pq, HH, K3D, 0);

    // 3. scores = Q K^T (batched)
    dim3 gScore(SS / 128, SS / 128, BB);
    gemm_bf16_nt<<<gScore, 256, GEMM_SMEM>>>(pqcat, (ll)SS * K3D, pkcat, (ll)SS * K3D,
                                             ps, nullptr, (ll)SS * SS, nullptr, nullptr,
                                             SS, K3D, 0);

    // 4. softmax fused with bf16x3 split -> pcat
    softmax_split<<<MT, 256>>>(ps, ppcat);

    // 5. V'^T split (B-side)
    cat_split_t<<<dim3(HH / 32, SS / 32, BB), dim3(32, 8)>>>(pv, pvt, SS, HH,
                                                             (ll)SS * HH, (ll)HH * K3S);

    // 6. context = P V'
    dim3 gCtx(HH / 128, SS / 128, BB);
    gemm_bf16_nt<<<gCtx, 256, GEMM_SMEM>>>(ppcat, (ll)SS * K3S, pvt, (ll)HH * K3S,
                                           out, nullptr, (ll)SS * HH, nullptr, nullptr,
                                           HH, K3S, 0);
}

// round 10
// speedup vs baseline: 2.4381x; 1.0092x over previous
#include <cuda_runtime.h>
#include <cuda_fp16.h>
#include <cuda_fp8.h>
#include <cstdint>

// Problem constants
#define BB 8
#define SS 2048
#define DD 768
#define HH 768
#define MT (BB*SS)        // 16384

typedef long long ll;

// ---------------------------------------------------------------------------
// Packed operand layout (per row, K = logical reduction length):
//   A-side: bytes [0,K)   = e4m3(a)
//           bytes [K,2K)  = e4m3((a - fp16(a)) * 4096)
//           bytes [2K,4K) = fp16(a)
//   B-side: bytes [0,K)   = e4m3((b - fp16(b)) * 4096)
//           bytes [K,2K)  = e4m3(b)
//           bytes [2K,4K) = fp16(b)
// fp8 phase (tiles 0..K/32-1) accumulates a*bl + al*b (x4096), then acc/=4096,
// fp16 phase (tiles K/32..2K/32-1) adds ah*bh. Row stride = 4K bytes.
// ---------------------------------------------------------------------------
__device__ __align__(16) uint8_t g_xp[(ll)MT * 4 * DD];
__device__ __align__(16) uint8_t g_yp[(ll)MT * 4 * DD];
__device__ __align__(16) uint8_t g_wp[3][(ll)HH * 4 * DD];
__device__ __align__(16) float   g_q [(ll)MT * HH];
__device__ __align__(16) float   g_v [(ll)MT * HH];           // V' = q ⊙ (yWv+bv)
__device__ __align__(16) uint8_t g_qp[(ll)MT * 4 * HH];       // A-side
__device__ __align__(16) uint8_t g_kp[(ll)MT * 4 * HH];       // B-side
__device__ __align__(16) float   g_s [(ll)BB * SS * SS];      // scores
__device__ __align__(16) uint8_t g_pp[(ll)MT * 4 * SS];       // probs, A-side
__device__ __align__(16) uint8_t g_vtp[(ll)BB * HH * 4 * SS]; // V'^T, B-side

// ---------------------------------------------------------------------------
// helpers
// ---------------------------------------------------------------------------
__device__ __forceinline__ uint32_t s2u(const void* p) {
    return (uint32_t)__cvta_generic_to_shared(p);
}
__device__ __forceinline__ uint8_t q8(float f) {
    return (uint8_t)__nv_cvt_float_to_fp8(f, __NV_SATFINITE, __NV_E4M3);
}
__device__ __forceinline__ void ldmx4(uint32_t* r, uint32_t a) {
    asm volatile("ldmatrix.sync.aligned.m8n8.x4.shared.b16 {%0,%1,%2,%3}, [%4];"
                 : "=r"(r[0]), "=r"(r[1]), "=r"(r[2]), "=r"(r[3]) : "r"(a));
}
__device__ __forceinline__ void mmaf16(float* c, const uint32_t* a, const uint32_t* b) {
    asm volatile("mma.sync.aligned.m16n8k16.row.col.f32.f16.f16.f32 "
                 "{%0,%1,%2,%3}, {%4,%5,%6,%7}, {%8,%9}, {%0,%1,%2,%3};"
                 : "+f"(c[0]), "+f"(c[1]), "+f"(c[2]), "+f"(c[3])
                 : "r"(a[0]), "r"(a[1]), "r"(a[2]), "r"(a[3]), "r"(b[0]), "r"(b[1]));
}
__device__ __forceinline__ void mmaf8(float* c, const uint32_t* a, const uint32_t* b) {
    asm volatile("mma.sync.aligned.m16n8k32.row.col.f32.e4m3.e4m3.f32 "
                 "{%0,%1,%2,%3}, {%4,%5,%6,%7}, {%8,%9}, {%0,%1,%2,%3};"
                 : "+f"(c[0]), "+f"(c[1]), "+f"(c[2]), "+f"(c[3])
                 : "r"(a[0]), "r"(a[1]), "r"(a[2]), "r"(a[3]), "r"(b[0]), "r"(b[1]));
}
__device__ __forceinline__ void cp16(uint32_t dst, const void* src) {
    asm volatile("cp.async.cg.shared.global [%0], [%1], 16;"
                 :: "r"(dst), "l"(src) : "memory");
}
__device__ __forceinline__ void cp_commit() {
    asm volatile("cp.async.commit_group;" ::: "memory");
}

// ---------------------------------------------------------------------------
// Mixed fp8/fp16 NT GEMM. Block tile 128x128, 8 warps (2x4), warp tile 64x32.
// Every K-tile = 64 data bytes per row (fp8: 64 elems, fp16: 32 elems).
// smem stage row = 80 bytes (64 data + 16 pad, conflict-free ldmatrix).
// ---------------------------------------------------------------------------
#define ROWB 80
#define MAT_BYTES (128 * ROWB)         // 10240
#define STG_BYTES (2 * MAT_BYTES)      // 20480
#define NSTAGE 4
#define GEMM_SMEM (NSTAGE * STG_BYTES) // 81920

__device__ __forceinline__ void issue_stage(const uint8_t* Ag, const uint8_t* Bg,
                                            ll rowB, int t, uint32_t sA,
                                            int lr, int lcB)
{
    const ll off = (ll)t * 64 + lcB;
    const uint32_t sB = sA + MAT_BYTES;
    cp16(sA + lr * ROWB + lcB,        Ag + (ll)lr * rowB + off);
    cp16(sA + (lr + 64) * ROWB + lcB, Ag + (ll)(lr + 64) * rowB + off);
    cp16(sB + lr * ROWB + lcB,        Bg + (ll)lr * rowB + off);
    cp16(sB + (lr + 64) * ROWB + lcB, Bg + (ll)(lr + 64) * rowB + off);
    cp_commit();
}

__global__ __launch_bounds__(256, 2)
void gemm_mix(const uint8_t* __restrict__ A, ll sAz,
              const uint8_t* __restrict__ B, ll sBz,
              float* __restrict__ Cf, uint8_t* __restrict__ Cpack, ll sCz,
              const float* __restrict__ bias,
              const float* __restrict__ mul,
              int N, int Kf, int side)   // Kf = logical K; side 0/1(A)/2(B) pack
{
    extern __shared__ char dyn[];
    const uint32_t sbase = s2u(dyn);

    const int tid = threadIdx.x;
    const int bx = blockIdx.x, by = blockIdx.y, z = blockIdx.z;
    const int lane = tid & 31, wid = tid >> 5;
    const int wm = (wid >> 2) * 64;
    const int wn = (wid & 3) * 32;

    const ll rowB = 4LL * Kf;
    const uint8_t* Ag = A + (ll)z * sAz + (ll)by * 128 * rowB;
    const uint8_t* Bg = B + (ll)z * sBz + (ll)bx * 128 * rowB;

    const int lr  = tid >> 2;
    const int lcB = (tid & 3) * 16;

    float acc[4][4][4];
    #pragma unroll
    for (int i = 0; i < 4; i++)
        #pragma unroll
        for (int j = 0; j < 4; j++)
            #pragma unroll
            for (int q = 0; q < 4; q++)
                acc[i][j][q] = 0.0f;

    // fragment smem BYTE offsets (per lane)
    const int aoff = (wm + (lane & 15)) * ROWB + (lane >> 4) * 16;
    const int bg4 = lane >> 3;
    const int boff = (wn + ((bg4 >> 1) * 8) + (lane & 7)) * ROWB + (bg4 & 1) * 16;

    const int nk8 = Kf / 32;       // fp8 tiles (2*Kf elems / 64)
    const int ntile = 2 * nk8;     // + fp16 tiles (Kf / 32)

    issue_stage(Ag, Bg, rowB, 0, sbase + 0 * STG_BYTES, lr, lcB);
    issue_stage(Ag, Bg, rowB, 1, sbase + 1 * STG_BYTES, lr, lcB);
    issue_stage(Ag, Bg, rowB, 2, sbase + 2 * STG_BYTES, lr, lcB);

    for (int kt = 0; kt < ntile; kt++) {
        asm volatile("cp.async.wait_group %0;" :: "n"(2) : "memory");
        __syncthreads();
        if (kt + 3 < ntile)
            issue_stage(Ag, Bg, rowB, kt + 3, sbase + ((kt + 3) & 3) * STG_BYTES, lr, lcB);

        if (kt == nk8) {   // fp8 partial complete: undo the 4096 lo prescale
            #pragma unroll
            for (int i = 0; i < 4; i++)
                #pragma unroll
                for (int j = 0; j < 4; j++)
                    #pragma unroll
                    for (int q = 0; q < 4; q++)
                        acc[i][j][q] *= 2.44140625e-4f;
        }

        const uint32_t abase = sbase + (kt & 3) * STG_BYTES;
        const uint32_t bbase = abase + MAT_BYTES;
        #pragma unroll
        for (int ks = 0; ks < 2; ks++) {
            uint32_t af[4][4], bfr[2][4];
            #pragma unroll
            for (int mi = 0; mi < 4; mi++)
                ldmx4(af[mi], abase + aoff + mi * 16 * ROWB + ks * 32);
            #pragma unroll
            for (int bj = 0; bj < 2; bj++)
                ldmx4(bfr[bj], bbase + boff + bj * 16 * ROWB + ks * 32);
            if (kt < nk8) {
                #pragma unroll
                for (int mi = 0; mi < 4; mi++)
                    #pragma unroll
                    for (int ni = 0; ni < 4; ni++)
                        mmaf8(acc[mi][ni], af[mi], &bfr[ni >> 1][(ni & 1) * 2]);
            } else {
                #pragma unroll
                for (int mi = 0; mi < 4; mi++)
                    #pragma unroll
                    for (int ni = 0; ni < 4; ni++)
                        mmaf16(acc[mi][ni], af[mi], &bfr[ni >> 1][(ni & 1) * 2]);
            }
        }
    }

    // --- epilogue ---
    const int gq = lane >> 2, tig = lane & 3;
    float* Cz = Cf ? (Cf + (ll)z * sCz) : nullptr;
    const float* Mz = mul ? (mul + (ll)z * sCz) : nullptr;

    #pragma unroll
    for (int mi = 0; mi < 4; mi++) {
        #pragma unroll
        for (int ni = 0; ni < 4; ni++) {
            const int row = by * 128 + wm + mi * 16 + gq;
            const int col = bx * 128 + wn + ni * 8 + tig * 2;
            float v0 = acc[mi][ni][0], v1 = acc[mi][ni][1];
            float v2 = acc[mi][ni][2], v3 = acc[mi][ni][3];
            if (bias) {
                float b0 = bias[col], b1 = bias[col + 1];
                v0 += b0; v1 += b1; v2 += b0; v3 += b1;
            }
            const ll o0 = (ll)row * N + col;
            const ll o1 = o0 + 8LL * N;
            if (Mz) {
                v0 *= Mz[o0]; v1 *= Mz[o0 + 1];
                v2 *= Mz[o1]; v3 *= Mz[o1 + 1];
            }
            if (Cz) {
                float2 r01; r01.x = v0; r01.y = v1;
                float2 r23; r23.x = v2; r23.y = v3;
                *reinterpret_cast<float2*>(Cz + o0) = r01;
                *reinterpret_cast<float2*>(Cz + o1) = r23;
            }
            if (side) {
                uint8_t* P0 = Cpack + (ll)row * (4LL * N);
                uint8_t* P1 = Cpack + (ll)(row + 8) * (4LL * N);
                __half h0 = __float2half_rn(v0), h1 = __float2half_rn(v1);
                __half h2 = __float2half_rn(v2), h3 = __float2half_rn(v3);
                float l0 = (v0 - __half2float(h0)) * 4096.f;
                float l1 = (v1 - __half2float(h1)) * 4096.f;
                float l2 = (v2 - __half2float(h2)) * 4096.f;
                float l3 = (v3 - __half2float(h3)) * 4096.f;
                uchar2 fA; fA.x = q8(v0); fA.y = q8(v1);
                uchar2 fB; fB.x = q8(v2); fB.y = q8(v3);
                uchar2 eA; eA.x = q8(l0); eA.y = q8(l1);
                uchar2 eB; eB.x = q8(l2); eB.y = q8(l3);
                __half2 hA; hA.x = h0; hA.y = h1;
                __half2 hB; hB.x = h2; hB.y = h3;
                if (side == 1) {   // A-side: [full8 | lo8 | fp16]
                    *reinterpret_cast<uchar2*>(P0 + col) = fA;
                    *reinterpret_cast<uchar2*>(P1 + col) = fB;
                    *reinterpret_cast<uchar2*>(P0 + N + col) = eA;
                    *reinterpret_cast<uchar2*>(P1 + N + col) = eB;
                } else {           // B-side: [lo8 | full8 | fp16]
                    *reinterpret_cast<uchar2*>(P0 + col) = eA;
                    *reinterpret_cast<uchar2*>(P1 + col) = eB;
                    *reinterpret_cast<uchar2*>(P0 + N + col) = fA;
                    *reinterpret_cast<uchar2*>(P1 + N + col) = fB;
                }
                *reinterpret_cast<__half2*>(P0 + 2LL * N + 2 * col) = hA;
                *reinterpret_cast<__half2*>(P1 + 2LL * N + 2 * col) = hB;
            }
        }
    }
}

// ---------------------------------------------------------------------------
// fp32 -> packed A-side split, src [R,C] -> dst rows of 4C bytes
// ---------------------------------------------------------------------------
__global__ void packA(const float* __restrict__ src, uint8_t* __restrict__ dst, int C)
{
    const ll r = blockIdx.y;
    const int c = blockIdx.x * 256 + threadIdx.x;
    float a = src[r * C + c];
    __half h = __float2half_rn(a);
    float lo = (a - __half2float(h)) * 4096.f;
    uint8_t* d = dst + r * (4LL * C);
    d[c] = q8(a);
    d[C + c] = q8(lo);
    reinterpret_cast<__half*>(d + 2LL * C)[c] = h;
}

// ---------------------------------------------------------------------------
// Transposed packed B-side split: src [P,Q] fp32 -> dst [Q rows, 4P bytes]
// ---------------------------------------------------------------------------
__global__ void packBT(const float* __restrict__ src, uint8_t* __restrict__ dst,
                       int P, int Q, ll sz, ll dz)
{
    __shared__ float t[32][33];
    const int z = blockIdx.z;
    const float* s = src + (ll)z * sz;
    uint8_t* d = dst + (ll)z * dz;
    const int c0 = blockIdx.x * 32, r0 = blockIdx.y * 32;  // c0 over Q, r0 over P
    const int tx = threadIdx.x, ty = threadIdx.y;

    #pragma unroll
    for (int i = 0; i < 4; i++)
        t[ty + 8 * i][tx] = s[(ll)(r0 + ty + 8 * i) * Q + c0 + tx];
    __syncthreads();
    #pragma unroll
    for (int i = 0; i < 4; i++) {
        float x = t[tx][ty + 8 * i];   // src[r0+tx][c0+ty+8i]
        __half h = __float2half_rn(x);
        float lo = (x - __half2float(h)) * 4096.f;
        uint8_t* dr = d + (ll)(c0 + ty + 8 * i) * (4LL * P);
        dr[r0 + tx] = q8(lo);
        dr[P + r0 + tx] = q8(x);
        reinterpret_cast<__half*>(dr + 2LL * P)[r0 + tx] = h;
    }
}

// ---------------------------------------------------------------------------
// Fused softmax + packed A-side split: scores row fp32 -> g_pp row (4*SS bytes)
// ---------------------------------------------------------------------------
__global__ void softmax_pack(const float* __restrict__ S, uint8_t* __restrict__ P)
{
    const ll row = blockIdx.x;
    const float* p = S + row * (ll)SS;
    uint8_t* d = P + row * (4LL * SS);
    const int t = threadIdx.x;
    __shared__ float red[32];

    float v[8];
    float m = -1e30f;
    #pragma unroll
    for (int i = 0; i < 8; i++) {
        v[i] = p[t + i * 256];
        m = fmaxf(m, v[i]);
    }
    #pragma unroll
    for (int o = 16; o > 0; o >>= 1) m = fmaxf(m, __shfl_xor_sync(0xffffffffu, m, o));
    if ((t & 31) == 0) red[t >> 5] = m;
    __syncthreads();
    if (t < 32) {
        float mm = (t < 8) ? red[t] : -1e30f;
        #pragma unroll
        for (int o = 16; o > 0; o >>= 1) mm = fmaxf(mm, __shfl_xor_sync(0xffffffffu, mm, o));
        if (t == 0) red[0] = mm;
    }
    __syncthreads();
    m = red[0];
    __syncthreads();

    float sum = 0.0f;
    #pragma unroll
    for (int i = 0; i < 8; i++) {
        v[i] = __expf(v[i] - m);
        sum += v[i];
    }
    #pragma unroll
    for (int o = 16; o > 0; o >>= 1) sum += __shfl_xor_sync(0xffffffffu, sum, o);
    if ((t & 31) == 0) red[t >> 5] = sum;
    __syncthreads();
    if (t < 32) {
        float ss = (t < 8) ? red[t] : 0.0f;
        #pragma unroll
        for (int o = 16; o > 0; o >>= 1) ss += __shfl_xor_sync(0xffffffffu, ss, o);
        if (t == 0) red[0] = ss;
    }
    __syncthreads();
    const float inv = 1.0f / red[0];

    #pragma unroll
    for (int i = 0; i < 8; i++) {
        const int c = t + i * 256;
        float pr = v[i] * inv;
        __half h = __float2half_rn(pr);
        float lo = (pr - __half2float(h)) * 4096.f;
        d[c] = q8(pr);
        d[SS + c] = q8(lo);
        reinterpret_cast<__half*>(d + 2LL * SS)[c] = h;
    }
}

// ---------------------------------------------------------------------------
extern "C" void kernel_launch(void* const* d_in, const int* in_sizes, int n_in,
                              void* d_out, int out_size)
{
    const float* x  = (const float*)d_in[0];
    const float* y  = (const float*)d_in[1];
    const float* Wq = (const float*)d_in[2];
    const float* bq = (const float*)d_in[3];
    const float* Wk = (const float*)d_in[4];
    const float* bk = (const float*)d_in[5];
    const float* Wv = (const float*)d_in[6];
    const float* bv = (const float*)d_in[7];
    float* out = (float*)d_out;

    uint8_t *pxp, *pyp, *pwp, *pqp, *pkp, *ppp, *pvtp;
    float *pq, *pv, *ps;
    cudaGetSymbolAddress((void**)&pxp,  g_xp);
    cudaGetSymbolAddress((void**)&pyp,  g_yp);
    cudaGetSymbolAddress((void**)&pwp,  g_wp);
    cudaGetSymbolAddress((void**)&pq,   g_q);
    cudaGetSymbolAddress((void**)&pv,   g_v);
    cudaGetSymbolAddress((void**)&pqp,  g_qp);
    cudaGetSymbolAddress((void**)&pkp,  g_kp);
    cudaGetSymbolAddress((void**)&ps,   g_s);
    cudaGetSymbolAddress((void**)&ppp,  g_pp);
    cudaGetSymbolAddress((void**)&pvtp, g_vtp);

    cudaFuncSetAttribute(gemm_mix, cudaFuncAttributeMaxDynamicSharedMemorySize,
                         GEMM_SMEM);

    const ll wStride = (ll)HH * 4 * DD;

    // 1. pack inputs + weights
    packA<<<dim3(DD / 256, MT), 256>>>(x, pxp, DD);
    packA<<<dim3(DD / 256, MT), 256>>>(y, pyp, DD);
    packBT<<<dim3(HH / 32, DD / 32, 1), dim3(32, 8)>>>(Wq, pwp + 0 * wStride, DD, HH, 0, 0);
    packBT<<<dim3(HH / 32, DD / 32, 1), dim3(32, 8)>>>(Wk, pwp + 1 * wStride, DD, HH, 0, 0);
    packBT<<<dim3(HH / 32, DD / 32, 1), dim3(32, 8)>>>(Wv, pwp + 2 * wStride, DD, HH, 0, 0);

    // 2. projections (fused pack epilogues)
    dim3 gProj(HH / 128, MT / 128, 1);
    // Q: fp32 q (gating) + A-side pack
    gemm_mix<<<gProj, 256, GEMM_SMEM>>>(pxp, 0, pwp + 0 * wStride, 0,
                                        pq, pqp, 0, bq, nullptr, HH, DD, 1);
    // K: B-side pack only
    gemm_mix<<<gProj, 256, GEMM_SMEM>>>(pxp, 0, pwp + 1 * wStride, 0,
                                        nullptr, pkp, 0, bk, nullptr, HH, DD, 2);
    // V': fp32 only, gated by q
    gemm_mix<<<gProj, 256, GEMM_SMEM>>>(pyp, 0, pwp + 2 * wStride, 0,
                                        pv, nullptr, 0, bv, pq, HH, DD, 0);

    // 3. scores = Q K^T (batched)
    dim3 gScore(SS / 128, SS / 128, BB);
    gemm_mix<<<gScore, 256, GEMM_SMEM>>>(pqp, (ll)SS * 4 * HH, pkp, (ll)SS * 4 * HH,
                                         ps, nullptr, (ll)SS * SS, nullptr, nullptr,
                                         SS, HH, 0);

    // 4. softmax + A-side pack
    softmax_pack<<<MT, 256>>>(ps, ppp);

    // 5. V'^T B-side pack (per batch)
    packBT<<<dim3(HH / 32, SS / 32, BB), dim3(32, 8)>>>(pv, pvtp, SS, HH,
                                                        (ll)SS * HH, (ll)HH * 4 * SS);

    // 6. context = P V'
    dim3 gCtx(HH / 128, SS / 128, BB);
    gemm_mix<<<gCtx, 256, GEMM_SMEM>>>(ppp, (ll)SS * 4 * SS, pvtp, (ll)HH * 4 * SS,
                                       out, nullptr, (ll)SS * HH, nullptr, nullptr,
                                       HH, SS, 0);
}